// round 1
// baseline (speedup 1.0000x reference)
#include <cuda_runtime.h>

// Guided filter: lr 256x256 (12 planes = 4 batch x 3 ch), hr 1024x1024.
// R=8 -> 17-tap clamped box window, separable.

#define RWIN 8
constexpr int H = 256, W = 256, PLANES = 12;
constexpr int HH = 1024, WH = 1024;
constexpr float EPSF  = 1e-8f;
constexpr float EPSSF = 1e-12f;
constexpr int PSZ = PLANES * H * W;          // one channel of low-res scratch

// ---- static device scratch (no allocation allowed) ----
__device__ float g_partial[768];
__device__ float g_invS;
__device__ float g_hsum[6 * PSZ];            // horizontal box sums, 6 products
__device__ float g_ab  [2 * PSZ];            // A, b
__device__ float g_hab [2 * PSZ];            // horizontal box sums of A, b
__device__ float g_mab [2 * PSZ];            // mean A, mean b (low-res)

// ---------- stage 0: sum(|l_a| + eps) over the whole tensor ----------
__global__ void k_reduce1(const float* __restrict__ la) {
    __shared__ float sm[256];
    int tid = threadIdx.x;
    int base = blockIdx.x * 1024;
    float s = 0.f;
#pragma unroll
    for (int k = 0; k < 4; k++)
        s += fabsf(la[base + k * 256 + tid]) + EPSSF;
    sm[tid] = s; __syncthreads();
    for (int off = 128; off > 0; off >>= 1) {
        if (tid < off) sm[tid] += sm[tid + off];
        __syncthreads();
    }
    if (tid == 0) g_partial[blockIdx.x] = sm[0];
}

__global__ void k_reduce2() {
    __shared__ float sm[256];
    int tid = threadIdx.x;
    float s = 0.f;
    for (int i = tid; i < 768; i += 256) s += g_partial[i];
    sm[tid] = s; __syncthreads();
    for (int off = 128; off > 0; off >>= 1) {
        if (tid < off) sm[tid] += sm[tid + off];
        __syncthreads();
    }
    if (tid == 0) g_invS = 1.0f / sm[0];
}

// ---------- stage 1: horizontal box sums of the 6 products ----------
__global__ void k_hbox(const float* __restrict__ lx,
                       const float* __restrict__ ly,
                       const float* __restrict__ la) {
    __shared__ float sp[6][W];
    int j = threadIdx.x;
    int base = blockIdx.x * W;                 // blockIdx.x = plane*H + row
    float a = fabsf(la[base + j]) + EPSSF;
    float x = lx[base + j];
    float y = ly[base + j];
    float ax = a * x;
    sp[0][j] = a;            // a
    sp[1][j] = ax * a * y;   // a^2 x y
    sp[2][j] = ax * a;       // a^2 x   (tax numerator, *invS later)
    sp[3][j] = a * y;        // a y
    sp[4][j] = ax * ax;      // a^2 x^2
    sp[5][j] = ax;           // a x
    __syncthreads();

    int lo = max(0, j - RWIN), hi = min(W - 1, j + RWIN);
    float s0=0,s1=0,s2=0,s3=0,s4=0,s5=0;
    for (int k = lo; k <= hi; k++) {
        s0 += sp[0][k]; s1 += sp[1][k]; s2 += sp[2][k];
        s3 += sp[3][k]; s4 += sp[4][k]; s5 += sp[5][k];
    }
    int o = base + j;
    g_hsum[0*PSZ + o] = s0;
    g_hsum[1*PSZ + o] = s1;
    g_hsum[2*PSZ + o] = s2;
    g_hsum[3*PSZ + o] = s3;
    g_hsum[4*PSZ + o] = s4;
    g_hsum[5*PSZ + o] = s5;
}

// ---------- stage 2: vertical box sums + compute A, b ----------
__global__ void k_vbox_ab() {
    int j = threadIdx.x;
    int pr = blockIdx.x;
    int plane = pr / H, row = pr % H;
    int pbase = plane * H * W;
    int lo = max(0, row - RWIN), hi = min(H - 1, row + RWIN);

    float s[6] = {0,0,0,0,0,0};
    for (int r = lo; r <= hi; r++) {
        int idx = pbase + r * W + j;
#pragma unroll
        for (int c = 0; c < 6; c++) s[c] += g_hsum[c * PSZ + idx];
    }
    float invS = g_invS;
    int nx = min(W - 1, j + RWIN) - max(0, j - RWIN) + 1;
    int ny = hi - lo + 1;
    float Nf = (float)(nx * ny);
    float invN = 1.0f / Nf;

    float m_a    = s[0] * invN;
    float m_a2xy = s[1] * invN;
    float m_tax  = invS * s[2] * invN;
    float m_ay   = s[3] * invN;
    float m_a2x2 = s[4] * invN;
    float m_ax   = s[5] * invN;

    float temp = fabsf(m_a2x2 - Nf * m_tax * m_ax);
    float A = (m_a2xy - Nf * m_tax * m_ay) / (temp + EPSF);
    float b = (m_ay - A * m_ax) / m_a;

    int o = pbase + row * W + j;
    g_ab[o]       = A;
    g_ab[PSZ + o] = b;
}

// ---------- stage 3: horizontal box sums of A, b ----------
__global__ void k_hbox2() {
    __shared__ float sA[W], sB[W];
    int j = threadIdx.x;
    int base = blockIdx.x * W;
    sA[j] = g_ab[base + j];
    sB[j] = g_ab[PSZ + base + j];
    __syncthreads();
    int lo = max(0, j - RWIN), hi = min(W - 1, j + RWIN);
    float a = 0.f, b = 0.f;
    for (int k = lo; k <= hi; k++) { a += sA[k]; b += sB[k]; }
    g_hab[base + j]       = a;
    g_hab[PSZ + base + j] = b;
}

// ---------- stage 4: vertical box sums of A, b -> means ----------
__global__ void k_vbox2() {
    int j = threadIdx.x;
    int pr = blockIdx.x;
    int plane = pr / H, row = pr % H;
    int pbase = plane * H * W;
    int lo = max(0, row - RWIN), hi = min(H - 1, row + RWIN);
    float a = 0.f, b = 0.f;
    for (int r = lo; r <= hi; r++) {
        int idx = pbase + r * W + j;
        a += g_hab[idx];
        b += g_hab[PSZ + idx];
    }
    int nx = min(W - 1, j + RWIN) - max(0, j - RWIN) + 1;
    float invN = 1.0f / (float)(nx * (hi - lo + 1));
    int o = pbase + row * W + j;
    g_mab[o]       = a * invN;
    g_mab[PSZ + o] = b * invN;
}

// ---------- stage 5: bilinear upsample 4x + fuse with hr_x ----------
__global__ void k_up(const float* __restrict__ hr, float* __restrict__ out) {
    int X = blockIdx.x * blockDim.x + threadIdx.x;
    int Y = blockIdx.y;
    int plane = blockIdx.z;
    const float sc = 255.0f / 1023.0f;
    float yf = Y * sc, xf = X * sc;
    int y0 = (int)yf, x0 = (int)xf;
    int y1 = min(y0 + 1, H - 1), x1 = min(x0 + 1, W - 1);
    float wy = yf - (float)y0, wx = xf - (float)x0;

    int pb = plane * H * W;
    const float* A = g_mab;
    const float* B = g_mab + PSZ;
    int i00 = pb + y0 * W + x0, i01 = pb + y0 * W + x1;
    int i10 = pb + y1 * W + x0, i11 = pb + y1 * W + x1;

    float Av = (A[i00] * (1.f - wy) + A[i10] * wy) * (1.f - wx)
             + (A[i01] * (1.f - wy) + A[i11] * wy) * wx;
    float Bv = (B[i00] * (1.f - wy) + B[i10] * wy) * (1.f - wx)
             + (B[i01] * (1.f - wy) + B[i11] * wy) * wx;

    int ho = plane * HH * WH + Y * WH + X;
    out[ho] = Av * hr[ho] + Bv;
}

extern "C" void kernel_launch(void* const* d_in, const int* in_sizes, int n_in,
                              void* d_out, int out_size) {
    const float* lr_x = (const float*)d_in[0];
    const float* lr_y = (const float*)d_in[1];
    const float* hr_x = (const float*)d_in[2];
    const float* l_a  = (const float*)d_in[3];
    float* out = (float*)d_out;

    k_reduce1<<<768, 256>>>(l_a);
    k_reduce2<<<1, 256>>>();
    k_hbox<<<PLANES * H, W>>>(lr_x, lr_y, l_a);
    k_vbox_ab<<<PLANES * H, W>>>();
    k_hbox2<<<PLANES * H, W>>>();
    k_vbox2<<<PLANES * H, W>>>();
    dim3 g(WH / 256, HH, PLANES);
    k_up<<<g, 256>>>(hr_x, out);
}